// round 12
// baseline (speedup 1.0000x reference)
#include <cuda_runtime.h>

#define BH    16
#define LQ    512
#define LK    512
#define DD    64
#define DMUFU 36     // d in [0,36): raw values, MUFU tanh path
#define DF    28     // d in [36,64): pre-tanh'd, formula path
#define TQ    16
#define TK    128

// Projected tensors, f32 [row][64]:
//   g_Wq: cols 0..35 = raw wq,  cols 36..63 = tanh(wq)
//   g_Wk: cols 0..35 = raw wk,  cols 36..63 = -tanh(wk)
__device__ float g_Wq[BH * LQ * DD];
__device__ float g_Wk[BH * LK * DD];

// ---------------------------------------------------------------------------
// Helpers
// ---------------------------------------------------------------------------
__device__ __forceinline__ float tanhapx(float x) {
    float y; asm("tanh.approx.f32 %0, %1;" : "=f"(y) : "f"(x)); return y;
}
__device__ __forceinline__ double f2x2(float lo, float hi) {
    double r; asm("mov.b64 %0, {%1, %2};" : "=d"(r) : "f"(lo), "f"(hi)); return r;
}
__device__ __forceinline__ void unpack2(double p, float& lo, float& hi) {
    asm("mov.b64 {%0, %1}, %2;" : "=f"(lo), "=f"(hi) : "d"(p));
}
__device__ __forceinline__ double addx2(double a, double b) {
    double r; asm("add.rn.f32x2 %0, %1, %2;" : "=d"(r) : "d"(a), "d"(b)); return r;
}
__device__ __forceinline__ double mulx2(double a, double b) {
    double r; asm("mul.rn.f32x2 %0, %1, %2;" : "=d"(r) : "d"(a), "d"(b)); return r;
}
__device__ __forceinline__ double fmx2(double a, double b, double c) {
    double r; asm("fma.rn.f32x2 %0, %1, %2, %3;" : "=d"(r) : "d"(a), "d"(b), "d"(c)); return r;
}
// Reciprocal seed of +D from bits of (-D): 0xFEF311C3 - bits(-D). D > 0.
__device__ __forceinline__ double rcp_seed_from_neg(double dn) {
    unsigned lo, hi;
    asm("mov.b64 {%0, %1}, %2;" : "=r"(lo), "=r"(hi) : "d"(dn));
    lo = 0xFEF311C3u - lo;
    hi = 0xFEF311C3u - hi;
    double r; asm("mov.b64 %0, {%1, %2};" : "=d"(r) : "r"(lo), "r"(hi)); return r;
}

// ---------------------------------------------------------------------------
// Fused projection kernel (fp32).
//   blocks [0,256):    Wq = Q*W1 + b1 ; cols 36..63 -> tanh
//   blocks [256,512):  Wk = K*W2 + b2 ; cols 36..63 -> -tanh
// ---------------------------------------------------------------------------
__global__ __launch_bounds__(256) void proj_fused_kernel(
    const float* __restrict__ Q, const float* __restrict__ K,
    const float* __restrict__ W1, const float* __restrict__ b1,
    const float* __restrict__ W2, const float* __restrict__ b2)
{
    __shared__ float Ws[DD][DD];
    __shared__ float Xs[32][DD + 1];

    const int  tid  = threadIdx.x;
    const bool isK  = (blockIdx.x >= 256);
    const int  blk  = isK ? (blockIdx.x - 256) : blockIdx.x;
    const int  rowBase = blk * 32;

    const float* __restrict__ X  = isK ? K  : Q;
    const float* __restrict__ W  = isK ? W2 : W1;
    const float* __restrict__ bb = isK ? b2 : b1;
    float* __restrict__ Out      = isK ? g_Wk : g_Wq;

    {
        const float4* src = (const float4*)W;
        float4* dst = (float4*)&Ws[0][0];
#pragma unroll
        for (int t = 0; t < 4; t++) dst[tid + t * 256] = src[tid + t * 256];
    }
#pragma unroll
    for (int t = 0; t < 8; t++) {
        int i = tid + t * 256;
        int r = i >> 6, c = i & 63;
        Xs[r][c] = X[(size_t)(rowBase + r) * DD + c];
    }
    __syncthreads();

    const int lane = tid & 31;
    const int eg   = tid >> 5;    // e-group: e = eg*8 + j

    float acc[8];
#pragma unroll
    for (int j = 0; j < 8; j++) acc[j] = __ldg(&bb[eg * 8 + j]);

#pragma unroll
    for (int d = 0; d < DD; d++) {
        const float xv = Xs[lane][d];
        const float4 w0 = *(const float4*)&Ws[d][eg * 8];
        const float4 w1 = *(const float4*)&Ws[d][eg * 8 + 4];
        acc[0] += xv * w0.x; acc[1] += xv * w0.y;
        acc[2] += xv * w0.z; acc[3] += xv * w0.w;
        acc[4] += xv * w1.x; acc[5] += xv * w1.y;
        acc[6] += xv * w1.z; acc[7] += xv * w1.w;
    }

    // Transform cols >= DMUFU: tanh (Q) or -tanh (K)
    {
        const float sgn = isK ? -1.0f : 1.0f;
#pragma unroll
        for (int j = 0; j < 8; j++)
            if (eg * 8 + j >= DMUFU) acc[j] = sgn * tanhapx(acc[j]);
    }

    __syncthreads();
#pragma unroll
    for (int j = 0; j < 8; j++) Xs[lane][eg * 8 + j] = acc[j];
    __syncthreads();
#pragma unroll
    for (int t = 0; t < 8; t++) {
        int i = tid + t * 256;
        int r = i >> 6, c = i & 63;
        Out[(size_t)(rowBase + r) * DD + c] = Xs[r][c];     // coalesced
    }
}

// ---------------------------------------------------------------------------
// Main kernel: 128-thread blocks, tile 16q x 128k, micro-tile 4x4 per warp,
// 6 CTAs/SM (smem 36.25KB, 85-reg cap). Fused loop: 4 MUFU d's + 4 formula d's
// per body; MUFU-only tail for d 28..35.
// Tight-stride split smem: wkm stride 36 (chunk 9, odd -> LDS.128 conflict-
// free), wkf stride 28 (chunk 7, odd -> conflict-free); wq reads broadcast.
// ---------------------------------------------------------------------------
__global__ __launch_bounds__(128, 6) void attn_main_kernel(
    const float* __restrict__ Vv, const float* __restrict__ bV,
    float* __restrict__ out)
{
    __shared__ __align__(16) float wqm_s[TQ][DMUFU];   // 16 x 36
    __shared__ __align__(16) float wqf_s[TQ][DF];      // 16 x 28
    __shared__ __align__(16) float wkm_s[TK][DMUFU];   // 128 x 36
    __shared__ __align__(16) float wkf_s[TK][DF];      // 128 x 28
    __shared__ __align__(16) float v_s[DD];

    const int bh    = blockIdx.z;
    const int qBase = blockIdx.y * TQ;
    const int kBase = blockIdx.x * TK;
    const int tid   = threadIdx.x;

    // ---- fill smem (coalesced global reads; split by column range) ----
    {
        const float* src = g_Wq + (size_t)(bh * LQ + qBase) * DD;
#pragma unroll
        for (int t = 0; t < 8; t++) {                 // 1024 = 16*64
            int i = tid + t * 128;
            int r = i >> 6, c = i & 63;
            float vv = src[i];
            if (c < DMUFU) wqm_s[r][c] = vv;
            else           wqf_s[r][c - DMUFU] = vv;
        }
    }
    {
        const float* src = g_Wk + (size_t)(bh * LK + kBase) * DD;
#pragma unroll
        for (int t = 0; t < 64; t++) {                // 8192 = 128*64
            int i = tid + t * 128;
            int r = i >> 6, c = i & 63;
            float vv = src[i];
            if (c < DMUFU) wkm_s[r][c] = vv;
            else           wkf_s[r][c - DMUFU] = vv;
        }
    }
    if (tid < DD) v_s[tid] = Vv[tid];
    __syncthreads();

    const int ty = tid >> 5;          // warp id (0..3) -> q rows ty*4 .. ty*4+3
    const int tx = tid & 31;          // k lane; k = j*32 + tx

    double acc[4][4];
#pragma unroll
    for (int i = 0; i < 4; i++)
#pragma unroll
        for (int j = 0; j < 4; j++) acc[i][j] = 0.0;

    const double ONE  = f2x2(1.0f, 1.0f);
    const double MONE = f2x2(-1.0f, -1.0f);

    // ======== fused: 7 iterations x (4 MUFU d's + 4 formula d's) ========
#pragma unroll 1
    for (int s2 = 0; s2 < 7; s2++) {
        const int cm = 4 * s2;            // MUFU cols cm..cm+3   (0..27)
        const int cf = 4 * s2;            // formula cols cf..cf+3 (0..27 in *f arrays)

        const float4 vmf = *(const float4*)&v_s[cm];
        const float4 vff = *(const float4*)&v_s[DMUFU + cf];
        const double vm0 = f2x2(vmf.x, vmf.y), vm1 = f2x2(vmf.z, vmf.w);
        const double vf0 = f2x2(vff.x, vff.y), vf1 = f2x2(vff.z, vff.w);

        float4 wkm4[4], wkf4[4];
#pragma unroll
        for (int j = 0; j < 4; j++) {
            wkm4[j] = *(const float4*)&wkm_s[j * 32 + tx][cm];   // LDS.128, stride 36: CF
            wkf4[j] = *(const float4*)&wkf_s[j * 32 + tx][cf];   // LDS.128, stride 28: CF
        }

#pragma unroll
        for (int i = 0; i < 4; i++) {
            const float4 wqm4 = *(const float4*)&wqm_s[ty * 4 + i][cm];   // broadcast
            const float4 wqf4 = *(const float4*)&wqf_s[ty * 4 + i][cf];
            const double wqm0 = f2x2(wqm4.x, wqm4.y), wqm1 = f2x2(wqm4.z, wqm4.w);
            const double tq0  = f2x2(wqf4.x, wqf4.y), tq1  = f2x2(wqf4.z, wqf4.w);

#pragma unroll
            for (int j = 0; j < 4; j++) {
                // ---- formula path first: start the reciprocal chains ----
                const double ntk0 = f2x2(wkf4[j].x, wkf4[j].y);
                const double ntk1 = f2x2(wkf4[j].z, wkf4[j].w);
                double nden0 = fmx2(tq0, ntk0, MONE);      // -(1 + tq*tk)
                double nden1 = fmx2(tq1, ntk1, MONE);
                double r0    = rcp_seed_from_neg(nden0);   // ~1/den (ALU)
                double r1    = rcp_seed_from_neg(nden1);

                // ---- MUFU path: 4 d's (tanh latency shadows Newton) ----
                double x0 = addx2(wqm0, f2x2(wkm4[j].x, wkm4[j].y));
                double x1 = addx2(wqm1, f2x2(wkm4[j].z, wkm4[j].w));
                float a0, a1, a2, a3;
                unpack2(x0, a0, a1);
                unpack2(x1, a2, a3);
                double t0 = f2x2(tanhapx(a0), tanhapx(a1));
                double t1 = f2x2(tanhapx(a2), tanhapx(a3));

                // ---- Newton refinement + formula accumulate ----
                double num0 = fmx2(ntk0, MONE, tq0);       // tq + tk
                double num1 = fmx2(ntk1, MONE, tq1);
                r0 = fmx2(r0, fmx2(nden0, r0, ONE), r0);   // Newton 1
                r1 = fmx2(r1, fmx2(nden1, r1, ONE), r1);
                r0 = fmx2(r0, fmx2(nden0, r0, ONE), r0);   // Newton 2
                r1 = fmx2(r1, fmx2(nden1, r1, ONE), r1);
                acc[i][j] = fmx2(mulx2(num0, r0), vf0, acc[i][j]);
                acc[i][j] = fmx2(mulx2(num1, r1), vf1, acc[i][j]);

                // ---- MUFU accumulate ----
                acc[i][j] = fmx2(t0, vm0, acc[i][j]);
                acc[i][j] = fmx2(t1, vm1, acc[i][j]);
            }
        }
    }

    // ======== MUFU-only tail: cols 28..35 (2 iterations of 4 d's) ========
#pragma unroll
    for (int s2 = 7; s2 < 9; s2++) {
        const int cm = 4 * s2;            // 28, 32
        const float4 vmf = *(const float4*)&v_s[cm];
        const double vm0 = f2x2(vmf.x, vmf.y), vm1 = f2x2(vmf.z, vmf.w);

        float4 wkm4[4];
#pragma unroll
        for (int j = 0; j < 4; j++)
            wkm4[j] = *(const float4*)&wkm_s[j * 32 + tx][cm];

#pragma unroll
        for (int i = 0; i < 4; i++) {
            const float4 wqm4 = *(const float4*)&wqm_s[ty * 4 + i][cm];
            const double wqm0 = f2x2(wqm4.x, wqm4.y), wqm1 = f2x2(wqm4.z, wqm4.w);
#pragma unroll
            for (int j = 0; j < 4; j++) {
                double x0 = addx2(wqm0, f2x2(wkm4[j].x, wkm4[j].y));
                double x1 = addx2(wqm1, f2x2(wkm4[j].z, wkm4[j].w));
                float a0, a1, a2, a3;
                unpack2(x0, a0, a1);
                unpack2(x1, a2, a3);
                double t0 = f2x2(tanhapx(a0), tanhapx(a1));
                double t1 = f2x2(tanhapx(a2), tanhapx(a3));
                acc[i][j] = fmx2(t0, vm0, acc[i][j]);
                acc[i][j] = fmx2(t1, vm1, acc[i][j]);
            }
        }
    }

    // ---- epilogue ----
    const float bv = bV[0];
#pragma unroll
    for (int i = 0; i < 4; i++) {
        const size_t rowOff = (size_t)(bh * LQ + qBase + ty * 4 + i) * LK + kBase;
#pragma unroll
        for (int j = 0; j < 4; j++) {
            float lo, hi;
            unpack2(acc[i][j], lo, hi);
            out[rowOff + j * 32 + tx] = lo + hi + bv;      // coalesced
        }
    }
}

// ---------------------------------------------------------------------------
// Launch
// ---------------------------------------------------------------------------
extern "C" void kernel_launch(void* const* d_in, const int* in_sizes, int n_in,
                              void* d_out, int out_size)
{
    const float* Q  = (const float*)d_in[0];
    const float* K  = (const float*)d_in[1];
    const float* W1 = (const float*)d_in[2];
    const float* b1 = (const float*)d_in[3];
    const float* W2 = (const float*)d_in[4];
    const float* b2 = (const float*)d_in[5];
    const float* V  = (const float*)d_in[6];
    const float* bV = (const float*)d_in[7];
    float* out = (float*)d_out;

    proj_fused_kernel<<<512, 256>>>(Q, K, W1, b1, W2, b2);

    dim3 grid(LK / TK, LQ / TQ, BH);                  // 4 x 32 x 16 = 2048
    attn_main_kernel<<<grid, 128>>>(V, bV, out);
}

// round 13
// speedup vs baseline: 1.1101x; 1.1101x over previous
#include <cuda_runtime.h>

#define BH    16
#define LQ    512
#define LK    512
#define DD    64
#define DMUFU 32     // d in [0,32): raw values, MUFU tanh path
#define TQ    16
#define TK    128
#define WPD   68     // smem row stride in floats: 272B, 16B-aligned, LDS.128 conflict-free

// Projected tensors, f32 [row][64]:
//   g_Wq: cols 0..31 = raw wq,  cols 32..63 = exp(2*wq)
//   g_Wk: cols 0..31 = raw wk,  cols 32..63 = -exp(2*wk)
__device__ float g_Wq[BH * LQ * DD];
__device__ float g_Wk[BH * LK * DD];

// ---------------------------------------------------------------------------
// Helpers
// ---------------------------------------------------------------------------
__device__ __forceinline__ float tanhapx(float x) {
    float y; asm("tanh.approx.f32 %0, %1;" : "=f"(y) : "f"(x)); return y;
}
__device__ __forceinline__ double f2x2(float lo, float hi) {
    double r; asm("mov.b64 %0, {%1, %2};" : "=d"(r) : "f"(lo), "f"(hi)); return r;
}
__device__ __forceinline__ void unpack2(double p, float& lo, float& hi) {
    asm("mov.b64 {%0, %1}, %2;" : "=f"(lo), "=f"(hi) : "d"(p));
}
__device__ __forceinline__ double addx2(double a, double b) {
    double r; asm("add.rn.f32x2 %0, %1, %2;" : "=d"(r) : "d"(a), "d"(b)); return r;
}
__device__ __forceinline__ double fmx2(double a, double b, double c) {
    double r; asm("fma.rn.f32x2 %0, %1, %2, %3;" : "=d"(r) : "d"(a), "d"(b), "d"(c)); return r;
}
// Reciprocal seed of +D from bits of (-D): 0xFEF311C3 - bits(-D). D > 0.
__device__ __forceinline__ double rcp_seed_from_neg(double dn) {
    unsigned lo, hi;
    asm("mov.b64 {%0, %1}, %2;" : "=r"(lo), "=r"(hi) : "d"(dn));
    lo = 0xFEF311C3u - lo;
    hi = 0xFEF311C3u - hi;
    double r; asm("mov.b64 %0, {%1, %2};" : "=d"(r) : "r"(lo), "r"(hi)); return r;
}

// ---------------------------------------------------------------------------
// Fused projection kernel (fp32, packed f32x2 inner loop).
//   blocks [0,256):    Wq = Q*W1 + b1 ; cols 32..63 -> exp(2x)
//   blocks [256,512):  Wk = K*W2 + b2 ; cols 32..63 -> -exp(2x)
// ---------------------------------------------------------------------------
__global__ __launch_bounds__(256) void proj_fused_kernel(
    const float* __restrict__ Q, const float* __restrict__ K,
    const float* __restrict__ W1, const float* __restrict__ b1,
    const float* __restrict__ W2, const float* __restrict__ b2)
{
    __shared__ __align__(16) float Ws[DD][DD];
    __shared__ float Xs[32][DD + 1];

    const int  tid  = threadIdx.x;
    const bool isK  = (blockIdx.x >= 256);
    const int  blk  = isK ? (blockIdx.x - 256) : blockIdx.x;
    const int  rowBase = blk * 32;

    const float* __restrict__ X  = isK ? K  : Q;
    const float* __restrict__ W  = isK ? W2 : W1;
    const float* __restrict__ bb = isK ? b2 : b1;
    float* __restrict__ Out      = isK ? g_Wk : g_Wq;

    {
        const float4* src = (const float4*)W;
        float4* dst = (float4*)&Ws[0][0];
#pragma unroll
        for (int t = 0; t < 4; t++) dst[tid + t * 256] = src[tid + t * 256];
    }
#pragma unroll
    for (int t = 0; t < 8; t++) {
        int i = tid + t * 256;
        int r = i >> 6, c = i & 63;
        Xs[r][c] = X[(size_t)(rowBase + r) * DD + c];
    }
    __syncthreads();

    const int lane = tid & 31;
    const int eg   = tid >> 5;    // e-group: e = eg*8 + j

    double accp[4];               // packed f32 pairs: e = eg*8 + {0,1},{2,3},{4,5},{6,7}
#pragma unroll
    for (int n = 0; n < 4; n++)
        accp[n] = f2x2(__ldg(&bb[eg * 8 + 2 * n]), __ldg(&bb[eg * 8 + 2 * n + 1]));

#pragma unroll
    for (int d = 0; d < DD; d++) {
        const float xv = Xs[lane][d];
        const double xvp = f2x2(xv, xv);
        const double2 wA = *(const double2*)&Ws[d][eg * 8];      // pairs (0,1),(2,3)
        const double2 wB = *(const double2*)&Ws[d][eg * 8 + 4];  // pairs (4,5),(6,7)
        accp[0] = fmx2(xvp, wA.x, accp[0]);
        accp[1] = fmx2(xvp, wA.y, accp[1]);
        accp[2] = fmx2(xvp, wB.x, accp[2]);
        accp[3] = fmx2(xvp, wB.y, accp[3]);
    }

    float acc[8];
#pragma unroll
    for (int n = 0; n < 4; n++) unpack2(accp[n], acc[2 * n], acc[2 * n + 1]);

    // Transform cols >= DMUFU: exp(2x) (Q) or -exp(2x) (K)
    if (eg >= 4) {
        const float sgn = isK ? -1.0f : 1.0f;
#pragma unroll
        for (int j = 0; j < 8; j++) acc[j] = sgn * __expf(2.0f * acc[j]);
    }

    __syncthreads();
#pragma unroll
    for (int j = 0; j < 8; j++) Xs[lane][eg * 8 + j] = acc[j];
    __syncthreads();
#pragma unroll
    for (int t = 0; t < 8; t++) {
        int i = tid + t * 256;
        int r = i >> 6, c = i & 63;
        Out[(size_t)(rowBase + r) * DD + c] = Xs[r][c];     // coalesced
    }
}

// ---------------------------------------------------------------------------
// Main kernel: 128-thread blocks, tile 16q x 128k, 4x4 micro-tile per warp.
// 8 fused iterations, each: 4 MUFU d's + 4 formula d's per (q,k):
//   MUFU:    addx2 -> tanh.approx.f32 x2 -> packed fma          (d 0..31)
//   formula: tanh(wq+wk) = 1 - 2/(1 + eq*ek); the 1 folds into the bias.
//            nden = fma(eq,nek,-1); magic seed + 2 Newton; acc += r*(-2v)
//            -> 6 FMA-ops per pair, zero MUFU                    (d 32..63)
// v_s[32..63] stores -2*v; bias gets +sum(v) over formula d's.
// ---------------------------------------------------------------------------
__global__ __launch_bounds__(128, 5) void attn_main_kernel(
    const float* __restrict__ Vv, const float* __restrict__ bV,
    float* __restrict__ out)
{
    __shared__ __align__(16) float wq_s[TQ][WPD];    // 16 x 68
    __shared__ __align__(16) float wk_s[TK][WPD];    // 128 x 68
    __shared__ __align__(16) float v_s[DD];

    const int bh    = blockIdx.z;
    const int qBase = blockIdx.y * TQ;
    const int kBase = blockIdx.x * TK;
    const int tid   = threadIdx.x;

    // ---- fill smem (coalesced global reads, padded stores) ----
    {
        const float* src = g_Wq + (size_t)(bh * LQ + qBase) * DD;
#pragma unroll
        for (int t = 0; t < 8; t++) {                 // 1024 = 16*64
            int i = tid + t * 128;
            wq_s[i >> 6][i & 63] = src[i];
        }
    }
    {
        const float* src = g_Wk + (size_t)(bh * LK + kBase) * DD;
#pragma unroll
        for (int t = 0; t < 64; t++) {                // 8192 = 128*64
            int i = tid + t * 128;
            wk_s[i >> 6][i & 63] = src[i];
        }
    }
    if (tid < DD) {
        float vv = Vv[tid];
        v_s[tid] = (tid < DMUFU) ? vv : (-2.0f * vv);
    }
    __syncthreads();

    const int ty = tid >> 5;          // warp id (0..3) -> q rows ty*4 .. ty*4+3
    const int tx = tid & 31;          // k lane; k = j*32 + tx

    double acc[4][4];
#pragma unroll
    for (int i = 0; i < 4; i++)
#pragma unroll
        for (int j = 0; j < 4; j++) acc[i][j] = 0.0;

    const double ONE  = f2x2(1.0f, 1.0f);
    const double MONE = f2x2(-1.0f, -1.0f);

    // ======== 8 fused iterations x (4 MUFU d's + 4 formula d's) ========
#pragma unroll 1
    for (int s2 = 0; s2 < 8; s2++) {
        const int cm = 4 * s2;            // MUFU cols    (0..31)
        const int cf = DMUFU + 4 * s2;    // formula cols (32..63)

        const double2 vm2  = *(const double2*)&v_s[cm];   // v pairs
        const double2 m2v2 = *(const double2*)&v_s[cf];   // -2v pairs

        double2 wkm2[4], wkf2[4];
#pragma unroll
        for (int j = 0; j < 4; j++) {
            wkm2[j] = *(const double2*)&wk_s[j * 32 + tx][cm];   // LDS.128, stride 68: CF
            wkf2[j] = *(const double2*)&wk_s[j * 32 + tx][cf];   // nek pairs
        }

#pragma unroll
        for (int i = 0; i < 4; i++) {
            const double2 wqm2 = *(const double2*)&wq_s[ty * 4 + i][cm];  // broadcast
            const double2 eq2  = *(const double2*)&wq_s[ty * 4 + i][cf];

#pragma unroll
            for (int j = 0; j < 4; j++) {
                // ---- formula: start reciprocal chains (zero MUFU) ----
                double nden0 = fmx2(eq2.x, wkf2[j].x, MONE);   // -(1 + eq*ek)
                double nden1 = fmx2(eq2.y, wkf2[j].y, MONE);
                double r0    = rcp_seed_from_neg(nden0);       // ~1/den (ALU)
                double r1    = rcp_seed_from_neg(nden1);

                // ---- MUFU path: 4 d's (tanh shadows Newton latency) ----
                double x0 = addx2(wqm2.x, wkm2[j].x);
                double x1 = addx2(wqm2.y, wkm2[j].y);
                float a0, a1, a2, a3;
                unpack2(x0, a0, a1);
                unpack2(x1, a2, a3);
                double t0 = f2x2(tanhapx(a0), tanhapx(a1));
                double t1 = f2x2(tanhapx(a2), tanhapx(a3));

                // ---- Newton refinement + formula accumulate ----
                r0 = fmx2(r0, fmx2(nden0, r0, ONE), r0);       // Newton 1
                r1 = fmx2(r1, fmx2(nden1, r1, ONE), r1);
                r0 = fmx2(r0, fmx2(nden0, r0, ONE), r0);       // Newton 2
                r1 = fmx2(r1, fmx2(nden1, r1, ONE), r1);
                acc[i][j] = fmx2(r0, m2v2.x, acc[i][j]);       // += (-2v) * r
                acc[i][j] = fmx2(r1, m2v2.y, acc[i][j]);

                // ---- MUFU accumulate ----
                acc[i][j] = fmx2(t0, vm2.x, acc[i][j]);
                acc[i][j] = fmx2(t1, vm2.y, acc[i][j]);
            }
        }
    }

    // ---- epilogue: bias + sum(v) over formula d's (v = -0.5 * stored -2v) ----
    float vsum = 0.0f;
#pragma unroll
    for (int c = 0; c < DD - DMUFU; c++) vsum += v_s[DMUFU + c];
    const float bv = bV[0] - 0.5f * vsum;

#pragma unroll
    for (int i = 0; i < 4; i++) {
        const size_t rowOff = (size_t)(bh * LQ + qBase + ty * 4 + i) * LK + kBase;
#pragma unroll
        for (int j = 0; j < 4; j++) {
            float lo, hi;
            unpack2(acc[i][j], lo, hi);
            out[rowOff + j * 32 + tx] = lo + hi + bv;      // coalesced
        }
    }
}

// ---------------------------------------------------------------------------
// Launch
// ---------------------------------------------------------------------------
extern "C" void kernel_launch(void* const* d_in, const int* in_sizes, int n_in,
                              void* d_out, int out_size)
{
    const float* Q  = (const float*)d_in[0];
    const float* K  = (const float*)d_in[1];
    const float* W1 = (const float*)d_in[2];
    const float* b1 = (const float*)d_in[3];
    const float* W2 = (const float*)d_in[4];
    const float* b2 = (const float*)d_in[5];
    const float* V  = (const float*)d_in[6];
    const float* bV = (const float*)d_in[7];
    float* out = (float*)d_out;

    proj_fused_kernel<<<512, 256>>>(Q, K, W1, b1, W2, b2);

    dim3 grid(LK / TK, LQ / TQ, BH);                  // 4 x 32 x 16 = 2048
    attn_main_kernel<<<grid, 128>>>(V, bV, out);
}